// round 3
// baseline (speedup 1.0000x reference)
#include <cuda_runtime.h>
#include <math.h>

// Problem constants (fixed by the reference setup)
#define NN 100000
#define NE 1600000
#define FD 128            // feature dim (in = hid = out = 128)
#define FD4 (FD/4)

// ---------------- static device scratch (no allocation allowed) ----------------
__device__ float g_h0[(size_t)NN * FD];     // ping
__device__ float g_h1[(size_t)NN * FD];     // pong
__device__ float g_agg[(size_t)NN * FD];    // aggregation buffer
__device__ int   g_cnt_src[NN];
__device__ int   g_cnt_dst[NN];
__device__ float g_norm_src[NN];
__device__ float g_norm_dst[NN];

// ---------------- small setup kernels ----------------
__global__ void zero_counts_kernel() {
    int i = blockIdx.x * blockDim.x + threadIdx.x;
    if (i < NN) { g_cnt_src[i] = 0; g_cnt_dst[i] = 0; }
}

__global__ void count_deg_kernel(const int* __restrict__ src,
                                 const int* __restrict__ dst) {
    int i = blockIdx.x * blockDim.x + threadIdx.x;
    if (i < NE) {
        atomicAdd(&g_cnt_src[src[i]], 1);
        atomicAdd(&g_cnt_dst[dst[i]], 1);
    }
}

__global__ void make_norm_kernel() {
    int i = blockIdx.x * blockDim.x + threadIdx.x;
    if (i < NN) {
        g_norm_src[i] = rsqrtf(fmaxf((float)g_cnt_src[i], 1.0f));
        g_norm_dst[i] = rsqrtf(fmaxf((float)g_cnt_dst[i], 1.0f));
    }
}

__global__ void zero_agg_kernel() {
    int i = blockIdx.x * blockDim.x + threadIdx.x;
    int n4 = NN * FD4;
    if (i < n4) ((float4*)g_agg)[i] = make_float4(0.f, 0.f, 0.f, 0.f);
}

// ---------------- edge scatter: agg[dst] += h[src] * norm_src[src] ----------------
// one warp per edge; each lane moves a float4 (128 floats per edge).
__global__ void __launch_bounds__(256) scatter_edges_kernel(
    const float* __restrict__ hin,
    const int* __restrict__ src,
    const int* __restrict__ dst)
{
    int gtid = blockIdx.x * blockDim.x + threadIdx.x;
    int e    = gtid >> 5;
    int lane = threadIdx.x & 31;
    if (e >= NE) return;

    int s = __ldg(&src[e]);          // broadcast load (all lanes same addr)
    int d = __ldg(&dst[e]);
    float ns = __ldg(&g_norm_src[s]);

    float4 v = __ldg(&((const float4*)(hin + (size_t)s * FD))[lane]);
    v.x *= ns; v.y *= ns; v.z *= ns; v.w *= ns;

    float* ap = g_agg + (size_t)d * FD + lane * 4;
    asm volatile("red.global.add.v4.f32 [%0], {%1,%2,%3,%4};"
                 :: "l"(ap), "f"(v.x), "f"(v.y), "f"(v.z), "f"(v.w)
                 : "memory");
}

// ---------------- GEMM + epilogue: out = act( (agg * norm_dst) @ W + b ) -------
// Block: 256 threads, 64 output rows x 128 cols. W (128x128, 64KB) + A tile
// (64x128, 32KB) staged in dynamic smem. Each thread computes 8 rows x 4 cols.
__device__ __forceinline__ float gelu_exact(float x) {
    return 0.5f * x * (1.0f + erff(x * 0.7071067811865476f));
}

template <bool GELU>
__global__ void __launch_bounds__(256) gemm_epi_kernel(
    const float* __restrict__ A,      // [NN, FD]  (agg, un-normalized by dst)
    const float* __restrict__ W,      // [FD, FD]  row-major (k, c)
    const float* __restrict__ bias,   // [FD]
    float* __restrict__ out)          // [NN, FD]
{
    extern __shared__ float sm[];
    float* sW = sm;                   // 128*128
    float* sA = sm + FD * FD;         // 64*128
    int tid = threadIdx.x;

    // stage W
    {
        float4* sW4 = (float4*)sW;
        const float4* W4 = (const float4*)W;
        #pragma unroll
        for (int i = 0; i < 16; ++i)   // 4096 float4 / 256 threads
            sW4[tid + i * 256] = __ldg(&W4[tid + i * 256]);
    }
    // stage A tile (64 rows)
    int rowbase = blockIdx.x * 64;
    {
        float4* sA4 = (float4*)sA;
        #pragma unroll
        for (int i = 0; i < 8; ++i) {  // 2048 float4 / 256 threads
            int idx = tid + i * 256;
            int r   = idx >> 5;        // /32 float4 per row
            int c4  = idx & 31;
            int gr  = rowbase + r;
            float4 v = make_float4(0.f, 0.f, 0.f, 0.f);
            if (gr < NN)
                v = __ldg(&((const float4*)(A + (size_t)gr * FD))[c4]);
            sA4[idx] = v;
        }
    }
    __syncthreads();

    int tx = tid & 31;   // column quad: cols [tx*4, tx*4+4)
    int ty = tid >> 5;   // row group:  rows [ty*8, ty*8+8)

    float acc[8][4];
    #pragma unroll
    for (int i = 0; i < 8; ++i)
        #pragma unroll
        for (int j = 0; j < 4; ++j) acc[i][j] = 0.f;

    const float4* sW4 = (const float4*)sW;
    #pragma unroll 4
    for (int k = 0; k < FD; ++k) {
        float4 b4 = sW4[k * 32 + tx];          // conflict-free, full row per warp
        #pragma unroll
        for (int i = 0; i < 8; ++i) {
            float a = sA[(ty * 8 + i) * FD + k];  // broadcast within warp
            acc[i][0] += a * b4.x;
            acc[i][1] += a * b4.y;
            acc[i][2] += a * b4.z;
            acc[i][3] += a * b4.w;
        }
    }

    float4 bv = __ldg(&((const float4*)bias)[tx]);
    #pragma unroll
    for (int i = 0; i < 8; ++i) {
        int gr = rowbase + ty * 8 + i;
        if (gr >= NN) continue;
        float nd = __ldg(&g_norm_dst[gr]);
        float4 o;
        o.x = acc[i][0] * nd + bv.x;
        o.y = acc[i][1] * nd + bv.y;
        o.z = acc[i][2] * nd + bv.z;
        o.w = acc[i][3] * nd + bv.w;
        if (GELU) {
            o.x = gelu_exact(o.x); o.y = gelu_exact(o.y);
            o.z = gelu_exact(o.z); o.w = gelu_exact(o.w);
        }
        ((float4*)(out + (size_t)gr * FD))[tx] = o;
    }
}

// ---------------- LayerNorm over feature dim (eps=1e-5) ----------------
__global__ void __launch_bounds__(256) layernorm_kernel(
    const float* __restrict__ h,
    const float* __restrict__ gamma,
    const float* __restrict__ beta,
    float* __restrict__ out)
{
    int gtid = blockIdx.x * blockDim.x + threadIdx.x;
    int row  = gtid >> 5;
    int lane = threadIdx.x & 31;
    if (row >= NN) return;

    float4 v = __ldg(&((const float4*)(h + (size_t)row * FD))[lane]);
    float s = v.x + v.y + v.z + v.w;
    #pragma unroll
    for (int o = 16; o; o >>= 1) s += __shfl_xor_sync(0xFFFFFFFFu, s, o);
    float mu = s * (1.0f / FD);

    float dx = v.x - mu, dy = v.y - mu, dz = v.z - mu, dw = v.w - mu;
    float q = dx * dx + dy * dy + dz * dz + dw * dw;
    #pragma unroll
    for (int o = 16; o; o >>= 1) q += __shfl_xor_sync(0xFFFFFFFFu, q, o);
    float inv = rsqrtf(q * (1.0f / FD) + 1e-5f);

    float4 g = __ldg(&((const float4*)gamma)[lane]);
    float4 b = __ldg(&((const float4*)beta)[lane]);
    float4 o4;
    o4.x = dx * inv * g.x + b.x;
    o4.y = dy * inv * g.y + b.y;
    o4.z = dz * inv * g.z + b.z;
    o4.w = dw * inv * g.w + b.w;
    ((float4*)(out + (size_t)row * FD))[lane] = o4;
}

// ---------------- launch ----------------
extern "C" void kernel_launch(void* const* d_in, const int* in_sizes, int n_in,
                              void* d_out, int out_size)
{
    const float* x     = (const float*)d_in[0];
    const int*   src   = (const int*)  d_in[1];
    const int*   dst   = (const int*)  d_in[2];
    const float* Ws[4] = { (const float*)d_in[3], (const float*)d_in[5],
                           (const float*)d_in[7], (const float*)d_in[9] };
    const float* bs[4] = { (const float*)d_in[4], (const float*)d_in[6],
                           (const float*)d_in[8], (const float*)d_in[10] };
    const float* gamma = (const float*)d_in[11];
    const float* beta  = (const float*)d_in[12];
    float* out = (float*)d_out;

    float *h0, *h1, *agg;
    cudaGetSymbolAddress((void**)&h0,  g_h0);
    cudaGetSymbolAddress((void**)&h1,  g_h1);
    cudaGetSymbolAddress((void**)&agg, g_agg);

    const int smem = (FD * FD + 64 * FD) * (int)sizeof(float);  // 96 KB
    cudaFuncSetAttribute(gemm_epi_kernel<true>,
                         cudaFuncAttributeMaxDynamicSharedMemorySize, smem);
    cudaFuncSetAttribute(gemm_epi_kernel<false>,
                         cudaFuncAttributeMaxDynamicSharedMemorySize, smem);

    const int T = 256;
    // degree norms
    zero_counts_kernel<<<(NN + T - 1) / T, T>>>();
    count_deg_kernel<<<(NE + T - 1) / T, T>>>(src, dst);
    make_norm_kernel<<<(NN + T - 1) / T, T>>>();

    const int zero_blocks    = (NN * FD4 + T - 1) / T;
    const int scatter_blocks = (NE * 32 + T - 1) / T;   // warp per edge
    const int gemm_blocks    = (NN + 63) / 64;

    const float* hin[4]  = { x,  h0, h1, h0 };
    float*       hout[4] = { h0, h1, h0, h1 };

    for (int L = 0; L < 4; ++L) {
        zero_agg_kernel<<<zero_blocks, T>>>();
        scatter_edges_kernel<<<scatter_blocks, T>>>(hin[L], src, dst);
        if (L < 3)
            gemm_epi_kernel<true><<<gemm_blocks, T, smem>>>(agg, Ws[L], bs[L], hout[L]);
        else
            gemm_epi_kernel<false><<<gemm_blocks, T, smem>>>(agg, Ws[L], bs[L], hout[L]);
    }

    layernorm_kernel<<<(NN * 32 + T - 1) / T, T>>>(h1, gamma, beta, out);
}

// round 4
// speedup vs baseline: 1.3721x; 1.3721x over previous
#include <cuda_runtime.h>
#include <math.h>

#define NN 100000
#define NE 1600000
#define FD 128
#define FD4 (FD/4)
#define SCAN_T 1024
#define SCAN_B ((NN + SCAN_T - 1) / SCAN_T)   // 98

// ---------------- static device scratch ----------------
__device__ float g_h0[(size_t)NN * FD];
__device__ float g_h1[(size_t)NN * FD];
__device__ int   g_cnt_src[NN];
__device__ int   g_cnt_dst[NN];
__device__ float g_norm_src[NN];
__device__ float g_norm_dst[NN];
__device__ int   g_rowstart[NN];
__device__ int   g_fill[NN];
__device__ int   g_bsum[SCAN_B];
__device__ int   g_boff[SCAN_B];
__device__ int   g_csr_src[NE];

// ---------------- setup kernels ----------------
__global__ void zero_counts_kernel() {
    int i = blockIdx.x * blockDim.x + threadIdx.x;
    if (i < NN) { g_cnt_src[i] = 0; g_cnt_dst[i] = 0; }
}

__global__ void count_deg_kernel(const int* __restrict__ src,
                                 const int* __restrict__ dst) {
    int i = blockIdx.x * blockDim.x + threadIdx.x;
    if (i < NE) {
        atomicAdd(&g_cnt_src[src[i]], 1);
        atomicAdd(&g_cnt_dst[dst[i]], 1);
    }
}

__global__ void make_norm_kernel() {
    int i = blockIdx.x * blockDim.x + threadIdx.x;
    if (i < NN) {
        g_norm_src[i] = rsqrtf(fmaxf((float)g_cnt_src[i], 1.0f));
        g_norm_dst[i] = rsqrtf(fmaxf((float)g_cnt_dst[i], 1.0f));
    }
}

// block-level exclusive scan of g_cnt_dst
__global__ void __launch_bounds__(SCAN_T) scan_block_kernel() {
    __shared__ int s[SCAN_T];
    int t = threadIdx.x;
    int i = blockIdx.x * SCAN_T + t;
    int v = (i < NN) ? g_cnt_dst[i] : 0;
    s[t] = v;
    __syncthreads();
    #pragma unroll
    for (int off = 1; off < SCAN_T; off <<= 1) {
        int x = (t >= off) ? s[t - off] : 0;
        __syncthreads();
        s[t] += x;
        __syncthreads();
    }
    if (i < NN) g_rowstart[i] = s[t] - v;      // exclusive
    if (t == SCAN_T - 1) g_bsum[blockIdx.x] = s[t];
}

__global__ void scan_bsums_kernel() {
    __shared__ int s[128];
    int t = threadIdx.x;
    int v = (t < SCAN_B) ? g_bsum[t] : 0;
    s[t] = v;
    __syncthreads();
    #pragma unroll
    for (int off = 1; off < 128; off <<= 1) {
        int x = (t >= off) ? s[t - off] : 0;
        __syncthreads();
        s[t] += x;
        __syncthreads();
    }
    if (t < SCAN_B) g_boff[t] = s[t] - v;      // exclusive
}

__global__ void add_offsets_kernel() {
    int i = blockIdx.x * blockDim.x + threadIdx.x;
    if (i < NN) {
        int v = g_rowstart[i] + g_boff[i >> 10];
        g_rowstart[i] = v;
        g_fill[i] = v;
    }
}

__global__ void fill_csr_kernel(const int* __restrict__ src,
                                const int* __restrict__ dst) {
    int e = blockIdx.x * blockDim.x + threadIdx.x;
    if (e < NE) {
        int pos = atomicAdd(&g_fill[dst[e]], 1);
        g_csr_src[pos] = src[e];
    }
}

// x_scaled = x * norm_src   (one-time; later layers pre-scale in epilogue)
__global__ void scale_x_kernel(const float* __restrict__ x, float* __restrict__ o) {
    int i = blockIdx.x * blockDim.x + threadIdx.x;
    if (i < NN * FD4) {
        int row = i >> 5;
        float ns = __ldg(&g_norm_src[row]);
        float4 v = __ldg(&((const float4*)x)[i]);
        v.x *= ns; v.y *= ns; v.z *= ns; v.w *= ns;
        ((float4*)o)[i] = v;
    }
}

// ---------------- fused gather + GEMM + epilogue ----------------
// Block: 256 threads, 64 output rows. Phase 1: each warp gathers+sums 8 rows'
// in-neighborhoods into sA. Phase 2: register-blocked GEMM (8x4 per thread).
// Epilogue: *norm_dst + bias, optional GELU, optional *norm_src pre-scale.
__device__ __forceinline__ float gelu_exact(float x) {
    return 0.5f * x * (1.0f + erff(x * 0.7071067811865476f));
}

template <bool GELU, bool PRESCALE>
__global__ void __launch_bounds__(256) gcn_fused_kernel(
    const float* __restrict__ hin,    // [NN, FD], already *norm_src
    const float* __restrict__ W,      // [FD, FD]
    const float* __restrict__ bias,   // [FD]
    float* __restrict__ out)          // [NN, FD]
{
    extern __shared__ float sm[];
    float* sW = sm;                   // 128*128
    float* sA = sm + FD * FD;         // 64*128
    int tid  = threadIdx.x;
    int warp = tid >> 5;
    int lane = tid & 31;
    int rowbase = blockIdx.x * 64;

    // stage W
    {
        float4* sW4 = (float4*)sW;
        const float4* W4 = (const float4*)W;
        #pragma unroll
        for (int i = 0; i < 16; ++i)
            sW4[tid + i * 256] = __ldg(&W4[tid + i * 256]);
    }

    // gather phase: warp w handles rows [w*8, w*8+8)
    const float4* hp = (const float4*)hin;
    #pragma unroll 1
    for (int r = 0; r < 8; ++r) {
        int lrow = warp * 8 + r;
        int grow = rowbase + lrow;
        float4 acc = make_float4(0.f, 0.f, 0.f, 0.f);
        if (grow < NN) {
            int beg = __ldg(&g_rowstart[grow]);
            int end = beg + __ldg(&g_cnt_dst[grow]);
            int e = beg;
            for (; e + 4 <= end; e += 4) {
                int s0 = __ldg(&g_csr_src[e]);
                int s1 = __ldg(&g_csr_src[e + 1]);
                int s2 = __ldg(&g_csr_src[e + 2]);
                int s3 = __ldg(&g_csr_src[e + 3]);
                float4 v0 = __ldg(&hp[s0 * 32 + lane]);
                float4 v1 = __ldg(&hp[s1 * 32 + lane]);
                float4 v2 = __ldg(&hp[s2 * 32 + lane]);
                float4 v3 = __ldg(&hp[s3 * 32 + lane]);
                acc.x += v0.x + v1.x + v2.x + v3.x;
                acc.y += v0.y + v1.y + v2.y + v3.y;
                acc.z += v0.z + v1.z + v2.z + v3.z;
                acc.w += v0.w + v1.w + v2.w + v3.w;
            }
            for (; e < end; ++e) {
                int s0 = __ldg(&g_csr_src[e]);
                float4 v0 = __ldg(&hp[s0 * 32 + lane]);
                acc.x += v0.x; acc.y += v0.y; acc.z += v0.z; acc.w += v0.w;
            }
        }
        ((float4*)sA)[lrow * 32 + lane] = acc;
    }
    __syncthreads();

    // GEMM phase
    int tx = tid & 31;   // cols [tx*4, tx*4+4)
    int ty = tid >> 5;   // rows [ty*8, ty*8+8)
    float acc[8][4];
    #pragma unroll
    for (int i = 0; i < 8; ++i)
        #pragma unroll
        for (int j = 0; j < 4; ++j) acc[i][j] = 0.f;

    const float4* sW4 = (const float4*)sW;
    #pragma unroll 4
    for (int k = 0; k < FD; ++k) {
        float4 b4 = sW4[k * 32 + tx];
        #pragma unroll
        for (int i = 0; i < 8; ++i) {
            float a = sA[(ty * 8 + i) * FD + k];
            acc[i][0] += a * b4.x;
            acc[i][1] += a * b4.y;
            acc[i][2] += a * b4.z;
            acc[i][3] += a * b4.w;
        }
    }

    float4 bv = __ldg(&((const float4*)bias)[tx]);
    #pragma unroll
    for (int i = 0; i < 8; ++i) {
        int gr = rowbase + ty * 8 + i;
        if (gr >= NN) continue;
        float nd = __ldg(&g_norm_dst[gr]);
        float4 o;
        o.x = acc[i][0] * nd + bv.x;
        o.y = acc[i][1] * nd + bv.y;
        o.z = acc[i][2] * nd + bv.z;
        o.w = acc[i][3] * nd + bv.w;
        if (GELU) {
            o.x = gelu_exact(o.x); o.y = gelu_exact(o.y);
            o.z = gelu_exact(o.z); o.w = gelu_exact(o.w);
        }
        if (PRESCALE) {
            float ns = __ldg(&g_norm_src[gr]);
            o.x *= ns; o.y *= ns; o.z *= ns; o.w *= ns;
        }
        ((float4*)(out + (size_t)gr * FD))[tx] = o;
    }
}

// ---------------- LayerNorm ----------------
__global__ void __launch_bounds__(256) layernorm_kernel(
    const float* __restrict__ h,
    const float* __restrict__ gamma,
    const float* __restrict__ beta,
    float* __restrict__ out)
{
    int gtid = blockIdx.x * blockDim.x + threadIdx.x;
    int row  = gtid >> 5;
    int lane = threadIdx.x & 31;
    if (row >= NN) return;

    float4 v = __ldg(&((const float4*)(h + (size_t)row * FD))[lane]);
    float s = v.x + v.y + v.z + v.w;
    #pragma unroll
    for (int o = 16; o; o >>= 1) s += __shfl_xor_sync(0xFFFFFFFFu, s, o);
    float mu = s * (1.0f / FD);

    float dx = v.x - mu, dy = v.y - mu, dz = v.z - mu, dw = v.w - mu;
    float q = dx * dx + dy * dy + dz * dz + dw * dw;
    #pragma unroll
    for (int o = 16; o; o >>= 1) q += __shfl_xor_sync(0xFFFFFFFFu, q, o);
    float inv = rsqrtf(q * (1.0f / FD) + 1e-5f);

    float4 g = __ldg(&((const float4*)gamma)[lane]);
    float4 b = __ldg(&((const float4*)beta)[lane]);
    float4 o4;
    o4.x = dx * inv * g.x + b.x;
    o4.y = dy * inv * g.y + b.y;
    o4.z = dz * inv * g.z + b.z;
    o4.w = dw * inv * g.w + b.w;
    ((float4*)(out + (size_t)row * FD))[lane] = o4;
}

// ---------------- launch ----------------
extern "C" void kernel_launch(void* const* d_in, const int* in_sizes, int n_in,
                              void* d_out, int out_size)
{
    const float* x     = (const float*)d_in[0];
    const int*   src   = (const int*)  d_in[1];
    const int*   dst   = (const int*)  d_in[2];
    const float* Ws[4] = { (const float*)d_in[3], (const float*)d_in[5],
                           (const float*)d_in[7], (const float*)d_in[9] };
    const float* bs[4] = { (const float*)d_in[4], (const float*)d_in[6],
                           (const float*)d_in[8], (const float*)d_in[10] };
    const float* gamma = (const float*)d_in[11];
    const float* beta  = (const float*)d_in[12];
    float* out = (float*)d_out;

    float *h0, *h1;
    cudaGetSymbolAddress((void**)&h0, g_h0);
    cudaGetSymbolAddress((void**)&h1, g_h1);

    const int smem = (FD * FD + 64 * FD) * (int)sizeof(float);  // 96 KB
    cudaFuncSetAttribute(gcn_fused_kernel<true, true>,
                         cudaFuncAttributeMaxDynamicSharedMemorySize, smem);
    cudaFuncSetAttribute(gcn_fused_kernel<false, false>,
                         cudaFuncAttributeMaxDynamicSharedMemorySize, smem);

    const int T = 256;
    // degree norms + CSR build
    zero_counts_kernel<<<(NN + T - 1) / T, T>>>();
    count_deg_kernel<<<(NE + T - 1) / T, T>>>(src, dst);
    make_norm_kernel<<<(NN + T - 1) / T, T>>>();
    scan_block_kernel<<<SCAN_B, SCAN_T>>>();
    scan_bsums_kernel<<<1, 128>>>();
    add_offsets_kernel<<<(NN + T - 1) / T, T>>>();
    fill_csr_kernel<<<(NE + T - 1) / T, T>>>(src, dst);

    // pre-scale x by norm_src
    scale_x_kernel<<<(NN * FD4 + T - 1) / T, T>>>(x, h0);

    const int gemm_blocks = (NN + 63) / 64;
    // L1..L3: gelu + prescale; L4: plain
    gcn_fused_kernel<true,  true><<<gemm_blocks, T, smem>>>(h0, Ws[0], bs[0], h1);
    gcn_fused_kernel<true,  true><<<gemm_blocks, T, smem>>>(h1, Ws[1], bs[1], h0);
    gcn_fused_kernel<true,  true><<<gemm_blocks, T, smem>>>(h0, Ws[2], bs[2], h1);
    gcn_fused_kernel<false, false><<<gemm_blocks, T, smem>>>(h1, Ws[3], bs[3], h0);

    layernorm_kernel<<<(NN * 32 + T - 1) / T, T>>>(h0, gamma, beta, out);
}

// round 5
// speedup vs baseline: 1.5559x; 1.1339x over previous
#include <cuda_runtime.h>
#include <math.h>
#include <stdint.h>

#define NN 100000
#define NE 1600000
#define FD 128
#define FD4 (FD/4)
#define SCAN_T 1024
#define SCAN_B ((NN + SCAN_T - 1) / SCAN_T)   // 98

// padded smem strides (floats) for bank-conflict-free MMA fragment loads
#define SA_STR 132   // 64 rows
#define SW_STR 136   // 128 rows
#define SMEM_BYTES ((128*SW_STR + 64*SA_STR) * 4)   // 103,424 B

// ---------------- static device scratch ----------------
__device__ float g_h0[(size_t)NN * FD];
__device__ float g_h1[(size_t)NN * FD];
__device__ int   g_cnt_src[NN];
__device__ int   g_cnt_dst[NN];
__device__ float g_norm_src[NN];
__device__ float g_norm_dst[NN];
__device__ int   g_rowstart[NN];
__device__ int   g_fill[NN];
__device__ int   g_bsum[SCAN_B];
__device__ int   g_boff[SCAN_B];
__device__ int   g_csr_src[NE];

// ---------------- setup kernels ----------------
__global__ void zero_counts_kernel() {
    int i = blockIdx.x * blockDim.x + threadIdx.x;
    if (i < NN) { g_cnt_src[i] = 0; g_cnt_dst[i] = 0; }
}

__global__ void count_deg_kernel(const int* __restrict__ src,
                                 const int* __restrict__ dst) {
    int i = blockIdx.x * blockDim.x + threadIdx.x;
    if (i < NE) {
        atomicAdd(&g_cnt_src[src[i]], 1);
        atomicAdd(&g_cnt_dst[dst[i]], 1);
    }
}

__global__ void make_norm_kernel() {
    int i = blockIdx.x * blockDim.x + threadIdx.x;
    if (i < NN) {
        g_norm_src[i] = rsqrtf(fmaxf((float)g_cnt_src[i], 1.0f));
        g_norm_dst[i] = rsqrtf(fmaxf((float)g_cnt_dst[i], 1.0f));
    }
}

__global__ void __launch_bounds__(SCAN_T) scan_block_kernel() {
    __shared__ int s[SCAN_T];
    int t = threadIdx.x;
    int i = blockIdx.x * SCAN_T + t;
    int v = (i < NN) ? g_cnt_dst[i] : 0;
    s[t] = v;
    __syncthreads();
    #pragma unroll
    for (int off = 1; off < SCAN_T; off <<= 1) {
        int x = (t >= off) ? s[t - off] : 0;
        __syncthreads();
        s[t] += x;
        __syncthreads();
    }
    if (i < NN) g_rowstart[i] = s[t] - v;
    if (t == SCAN_T - 1) g_bsum[blockIdx.x] = s[t];
}

__global__ void scan_bsums_kernel() {
    __shared__ int s[128];
    int t = threadIdx.x;
    int v = (t < SCAN_B) ? g_bsum[t] : 0;
    s[t] = v;
    __syncthreads();
    #pragma unroll
    for (int off = 1; off < 128; off <<= 1) {
        int x = (t >= off) ? s[t - off] : 0;
        __syncthreads();
        s[t] += x;
        __syncthreads();
    }
    if (t < SCAN_B) g_boff[t] = s[t] - v;
}

__global__ void add_offsets_kernel() {
    int i = blockIdx.x * blockDim.x + threadIdx.x;
    if (i < NN) {
        int v = g_rowstart[i] + g_boff[i >> 10];
        g_rowstart[i] = v;
        g_fill[i] = v;
    }
}

__global__ void fill_csr_kernel(const int* __restrict__ src,
                                const int* __restrict__ dst) {
    int e = blockIdx.x * blockDim.x + threadIdx.x;
    if (e < NE) {
        int pos = atomicAdd(&g_fill[dst[e]], 1);
        g_csr_src[pos] = src[e];
    }
}

__global__ void scale_x_kernel(const float* __restrict__ x, float* __restrict__ o) {
    int i = blockIdx.x * blockDim.x + threadIdx.x;
    if (i < NN * FD4) {
        int row = i >> 5;
        float ns = __ldg(&g_norm_src[row]);
        float4 v = __ldg(&((const float4*)x)[i]);
        v.x *= ns; v.y *= ns; v.z *= ns; v.w *= ns;
        ((float4*)o)[i] = v;
    }
}

// ---------------- tf32 helpers ----------------
__device__ __forceinline__ void f2tf32_split(float a, uint32_t& hi, uint32_t& lo) {
    asm("cvt.rna.tf32.f32 %0, %1;" : "=r"(hi) : "f"(a));
    float r = a - __uint_as_float(hi);
    asm("cvt.rna.tf32.f32 %0, %1;" : "=r"(lo) : "f"(r));
}

__device__ __forceinline__ void mma_tf32(float* c,
    uint32_t a0, uint32_t a1, uint32_t a2, uint32_t a3,
    uint32_t b0, uint32_t b1)
{
    asm volatile(
        "mma.sync.aligned.m16n8k8.row.col.f32.tf32.tf32.f32 "
        "{%0,%1,%2,%3}, {%4,%5,%6,%7}, {%8,%9}, {%0,%1,%2,%3};"
        : "+f"(c[0]), "+f"(c[1]), "+f"(c[2]), "+f"(c[3])
        : "r"(a0), "r"(a1), "r"(a2), "r"(a3), "r"(b0), "r"(b1));
}

__device__ __forceinline__ float gelu_exact(float x) {
    return 0.5f * x * (1.0f + erff(x * 0.7071067811865476f));
}

// ---------------- fused gather + tensor-core GEMM + epilogue ----------------
// Block: 256 threads (8 warps), 64 output rows x 128 cols.
// Gather: warp w sums in-neighborhoods of rows [w*8, w*8+8) into sA.
// GEMM: warp w computes rows [(w&3)*16, +16) x cols [(w>>2)*64, +64) with
//       3xTF32 mma.sync (fp32-equivalent precision).
template <bool GELU, bool PRESCALE>
__global__ void __launch_bounds__(256) gcn_fused_kernel(
    const float* __restrict__ hin,    // [NN, FD], already *norm_src
    const float* __restrict__ W,      // [FD, FD] row-major (k, n)
    const float* __restrict__ bias,   // [FD]
    float* __restrict__ out)          // [NN, FD]
{
    extern __shared__ float sm[];
    float* sW = sm;                       // 128 x SW_STR
    float* sA = sm + 128 * SW_STR;        // 64  x SA_STR
    int tid  = threadIdx.x;
    int warp = tid >> 5;
    int lane = tid & 31;
    int rowbase = blockIdx.x * 64;

    // stage W (padded rows)
    {
        float4* sW4 = (float4*)sW;        // row stride SW_STR/4 = 34
        const float4* W4 = (const float4*)W;
        #pragma unroll
        for (int i = 0; i < 16; ++i) {
            int idx = tid + i * 256;      // [0, 4096)
            int k  = idx >> 5;
            int n4 = idx & 31;
            sW4[k * 34 + n4] = __ldg(&W4[idx]);
        }
    }

    // gather phase: warp w handles rows [w*8, w*8+8)
    const float4* hp = (const float4*)hin;
    #pragma unroll 1
    for (int r = 0; r < 8; ++r) {
        int lrow = warp * 8 + r;
        int grow = rowbase + lrow;
        float4 acc = make_float4(0.f, 0.f, 0.f, 0.f);
        if (grow < NN) {
            int beg = __ldg(&g_rowstart[grow]);
            int end = beg + __ldg(&g_cnt_dst[grow]);
            int e = beg;
            for (; e + 8 <= end; e += 8) {
                int s0 = __ldg(&g_csr_src[e]);
                int s1 = __ldg(&g_csr_src[e + 1]);
                int s2 = __ldg(&g_csr_src[e + 2]);
                int s3 = __ldg(&g_csr_src[e + 3]);
                int s4 = __ldg(&g_csr_src[e + 4]);
                int s5 = __ldg(&g_csr_src[e + 5]);
                int s6 = __ldg(&g_csr_src[e + 6]);
                int s7 = __ldg(&g_csr_src[e + 7]);
                float4 v0 = __ldg(&hp[s0 * 32 + lane]);
                float4 v1 = __ldg(&hp[s1 * 32 + lane]);
                float4 v2 = __ldg(&hp[s2 * 32 + lane]);
                float4 v3 = __ldg(&hp[s3 * 32 + lane]);
                float4 v4 = __ldg(&hp[s4 * 32 + lane]);
                float4 v5 = __ldg(&hp[s5 * 32 + lane]);
                float4 v6 = __ldg(&hp[s6 * 32 + lane]);
                float4 v7 = __ldg(&hp[s7 * 32 + lane]);
                acc.x += ((v0.x + v1.x) + (v2.x + v3.x)) + ((v4.x + v5.x) + (v6.x + v7.x));
                acc.y += ((v0.y + v1.y) + (v2.y + v3.y)) + ((v4.y + v5.y) + (v6.y + v7.y));
                acc.z += ((v0.z + v1.z) + (v2.z + v3.z)) + ((v4.z + v5.z) + (v6.z + v7.z));
                acc.w += ((v0.w + v1.w) + (v2.w + v3.w)) + ((v4.w + v5.w) + (v6.w + v7.w));
            }
            for (; e < end; ++e) {
                int s0 = __ldg(&g_csr_src[e]);
                float4 v0 = __ldg(&hp[s0 * 32 + lane]);
                acc.x += v0.x; acc.y += v0.y; acc.z += v0.z; acc.w += v0.w;
            }
        }
        ((float4*)sA)[lrow * (SA_STR / 4) + lane] = acc;   // SA_STR/4 = 33
    }
    __syncthreads();

    // ---- tensor-core GEMM: D[64x128] = sA[64x128] @ sW[128x128] (3xTF32) ----
    int g = lane >> 2;        // 0..7
    int t = lane & 3;         // 0..3
    int rtbase = (warp & 3) * 16;      // row tile base (within block tile)
    int chbase = (warp >> 2) * 64;     // column half base

    float c[8][4];
    #pragma unroll
    for (int n = 0; n < 8; ++n)
        #pragma unroll
        for (int j = 0; j < 4; ++j) c[n][j] = 0.f;

    #pragma unroll 4
    for (int k = 0; k < 16; ++k) {
        int k0 = k * 8;
        // A fragment (m16k8, row-major), rows rtbase+g / rtbase+g+8
        float a0f = sA[(rtbase + g)     * SA_STR + k0 + t];
        float a1f = sA[(rtbase + g + 8) * SA_STR + k0 + t];
        float a2f = sA[(rtbase + g)     * SA_STR + k0 + t + 4];
        float a3f = sA[(rtbase + g + 8) * SA_STR + k0 + t + 4];
        uint32_t ah0, al0, ah1, al1, ah2, al2, ah3, al3;
        f2tf32_split(a0f, ah0, al0);
        f2tf32_split(a1f, ah1, al1);
        f2tf32_split(a2f, ah2, al2);
        f2tf32_split(a3f, ah3, al3);

        #pragma unroll
        for (int n = 0; n < 8; ++n) {
            // B fragment (k8 x n8, col-major view of W[k][n])
            int ncol = chbase + n * 8 + g;
            float b0f = sW[(k0 + t)     * SW_STR + ncol];
            float b1f = sW[(k0 + t + 4) * SW_STR + ncol];
            uint32_t bh0, bl0, bh1, bl1;
            f2tf32_split(b0f, bh0, bl0);
            f2tf32_split(b1f, bh1, bl1);

            mma_tf32(c[n], ah0, ah1, ah2, ah3, bh0, bh1);   // hi*hi
            mma_tf32(c[n], ah0, ah1, ah2, ah3, bl0, bl1);   // hi*lo
            mma_tf32(c[n], al0, al1, al2, al3, bh0, bh1);   // lo*hi
        }
    }

    // ---- epilogue ----
    int row0 = rowbase + rtbase + g;
    int row1 = row0 + 8;
    float nd0 = 0.f, nd1 = 0.f, ns0 = 1.f, ns1 = 1.f;
    if (row0 < NN) { nd0 = __ldg(&g_norm_dst[row0]); if (PRESCALE) ns0 = __ldg(&g_norm_src[row0]); }
    if (row1 < NN) { nd1 = __ldg(&g_norm_dst[row1]); if (PRESCALE) ns1 = __ldg(&g_norm_src[row1]); }

    #pragma unroll
    for (int n = 0; n < 8; ++n) {
        int col = chbase + n * 8 + t * 2;
        float2 bv = *(const float2*)(bias + col);
        if (row0 < NN) {
            float ox = c[n][0] * nd0 + bv.x;
            float oy = c[n][1] * nd0 + bv.y;
            if (GELU) { ox = gelu_exact(ox); oy = gelu_exact(oy); }
            if (PRESCALE) { ox *= ns0; oy *= ns0; }
            *(float2*)(out + (size_t)row0 * FD + col) = make_float2(ox, oy);
        }
        if (row1 < NN) {
            float ox = c[n][2] * nd1 + bv.x;
            float oy = c[n][3] * nd1 + bv.y;
            if (GELU) { ox = gelu_exact(ox); oy = gelu_exact(oy); }
            if (PRESCALE) { ox *= ns1; oy *= ns1; }
            *(float2*)(out + (size_t)row1 * FD + col) = make_float2(ox, oy);
        }
    }
}

// ---------------- LayerNorm ----------------
__global__ void __launch_bounds__(256) layernorm_kernel(
    const float* __restrict__ h,
    const float* __restrict__ gamma,
    const float* __restrict__ beta,
    float* __restrict__ out)
{
    int gtid = blockIdx.x * blockDim.x + threadIdx.x;
    int row  = gtid >> 5;
    int lane = threadIdx.x & 31;
    if (row >= NN) return;

    float4 v = __ldg(&((const float4*)(h + (size_t)row * FD))[lane]);
    float s = v.x + v.y + v.z + v.w;
    #pragma unroll
    for (int o = 16; o; o >>= 1) s += __shfl_xor_sync(0xFFFFFFFFu, s, o);
    float mu = s * (1.0f / FD);

    float dx = v.x - mu, dy = v.y - mu, dz = v.z - mu, dw = v.w - mu;
    float q = dx * dx + dy * dy + dz * dz + dw * dw;
    #pragma unroll
    for (int o = 16; o; o >>= 1) q += __shfl_xor_sync(0xFFFFFFFFu, q, o);
    float inv = rsqrtf(q * (1.0f / FD) + 1e-5f);

    float4 gm = __ldg(&((const float4*)gamma)[lane]);
    float4 bt = __ldg(&((const float4*)beta)[lane]);
    float4 o4;
    o4.x = dx * inv * gm.x + bt.x;
    o4.y = dy * inv * gm.y + bt.y;
    o4.z = dz * inv * gm.z + bt.z;
    o4.w = dw * inv * gm.w + bt.w;
    ((float4*)(out + (size_t)row * FD))[lane] = o4;
}

// ---------------- launch ----------------
extern "C" void kernel_launch(void* const* d_in, const int* in_sizes, int n_in,
                              void* d_out, int out_size)
{
    const float* x     = (const float*)d_in[0];
    const int*   src   = (const int*)  d_in[1];
    const int*   dst   = (const int*)  d_in[2];
    const float* Ws[4] = { (const float*)d_in[3], (const float*)d_in[5],
                           (const float*)d_in[7], (const float*)d_in[9] };
    const float* bs[4] = { (const float*)d_in[4], (const float*)d_in[6],
                           (const float*)d_in[8], (const float*)d_in[10] };
    const float* gamma = (const float*)d_in[11];
    const float* beta  = (const float*)d_in[12];
    float* out = (float*)d_out;

    float *h0, *h1;
    cudaGetSymbolAddress((void**)&h0, g_h0);
    cudaGetSymbolAddress((void**)&h1, g_h1);

    cudaFuncSetAttribute(gcn_fused_kernel<true, true>,
                         cudaFuncAttributeMaxDynamicSharedMemorySize, SMEM_BYTES);
    cudaFuncSetAttribute(gcn_fused_kernel<false, false>,
                         cudaFuncAttributeMaxDynamicSharedMemorySize, SMEM_BYTES);

    const int T = 256;
    zero_counts_kernel<<<(NN + T - 1) / T, T>>>();
    count_deg_kernel<<<(NE + T - 1) / T, T>>>(src, dst);
    make_norm_kernel<<<(NN + T - 1) / T, T>>>();
    scan_block_kernel<<<SCAN_B, SCAN_T>>>();
    scan_bsums_kernel<<<1, 128>>>();
    add_offsets_kernel<<<(NN + T - 1) / T, T>>>();
    fill_csr_kernel<<<(NE + T - 1) / T, T>>>(src, dst);

    scale_x_kernel<<<(NN * FD4 + T - 1) / T, T>>>(x, h0);

    const int gemm_blocks = (NN + 63) / 64;
    gcn_fused_kernel<true,  true><<<gemm_blocks, T, SMEM_BYTES>>>(h0, Ws[0], bs[0], h1);
    gcn_fused_kernel<true,  true><<<gemm_blocks, T, SMEM_BYTES>>>(h1, Ws[1], bs[1], h0);
    gcn_fused_kernel<true,  true><<<gemm_blocks, T, SMEM_BYTES>>>(h0, Ws[2], bs[2], h1);
    gcn_fused_kernel<false, false><<<gemm_blocks, T, SMEM_BYTES>>>(h1, Ws[3], bs[3], h0);

    layernorm_kernel<<<(NN * 32 + T - 1) / T, T>>>(h0, gamma, beta, out);
}

// round 6
// speedup vs baseline: 1.6472x; 1.0587x over previous
#include <cuda_runtime.h>
#include <math.h>
#include <stdint.h>

#define NN 100000
#define NE 1600000
#define FD 128
#define FD4 (FD/4)
#define SCAN_T 1024
#define SCAN_B ((NN + SCAN_T - 1) / SCAN_T)   // 98

// padded smem strides (floats) for bank-conflict-free MMA fragment loads
#define SA_STR 132   // 64 rows
#define SW_STR 136   // 128 rows
#define SMEM_BYTES ((128*SW_STR + 64*SA_STR) * 4)   // 103,424 B

// ---------------- static device scratch ----------------
__device__ float g_h0[(size_t)NN * FD];
__device__ float g_h1[(size_t)NN * FD];
__device__ int   g_cnt_src[NN];
__device__ int   g_cnt_dst[NN];
__device__ float g_norm_src[NN];
__device__ float g_norm_dst[NN];
__device__ int   g_rowstart[NN];
__device__ int   g_fill[NN];
__device__ int   g_bsum[SCAN_B];
__device__ int   g_boff[SCAN_B];
__device__ int   g_csr_src[NE];

// ---------------- setup kernels ----------------
__global__ void zero_counts_kernel() {
    int i = blockIdx.x * blockDim.x + threadIdx.x;
    if (i < NN) { g_cnt_src[i] = 0; g_cnt_dst[i] = 0; }
}

__global__ void count_deg_kernel(const int* __restrict__ src,
                                 const int* __restrict__ dst) {
    int i = blockIdx.x * blockDim.x + threadIdx.x;
    if (i < NE) {
        atomicAdd(&g_cnt_src[src[i]], 1);
        atomicAdd(&g_cnt_dst[dst[i]], 1);
    }
}

__global__ void make_norm_kernel() {
    int i = blockIdx.x * blockDim.x + threadIdx.x;
    if (i < NN) {
        g_norm_src[i] = rsqrtf(fmaxf((float)g_cnt_src[i], 1.0f));
        g_norm_dst[i] = rsqrtf(fmaxf((float)g_cnt_dst[i], 1.0f));
    }
}

__global__ void __launch_bounds__(SCAN_T) scan_block_kernel() {
    __shared__ int s[SCAN_T];
    int t = threadIdx.x;
    int i = blockIdx.x * SCAN_T + t;
    int v = (i < NN) ? g_cnt_dst[i] : 0;
    s[t] = v;
    __syncthreads();
    #pragma unroll
    for (int off = 1; off < SCAN_T; off <<= 1) {
        int x = (t >= off) ? s[t - off] : 0;
        __syncthreads();
        s[t] += x;
        __syncthreads();
    }
    if (i < NN) g_rowstart[i] = s[t] - v;
    if (t == SCAN_T - 1) g_bsum[blockIdx.x] = s[t];
}

__global__ void scan_bsums_kernel() {
    __shared__ int s[128];
    int t = threadIdx.x;
    int v = (t < SCAN_B) ? g_bsum[t] : 0;
    s[t] = v;
    __syncthreads();
    #pragma unroll
    for (int off = 1; off < 128; off <<= 1) {
        int x = (t >= off) ? s[t - off] : 0;
        __syncthreads();
        s[t] += x;
        __syncthreads();
    }
    if (t < SCAN_B) g_boff[t] = s[t] - v;
}

__global__ void add_offsets_kernel() {
    int i = blockIdx.x * blockDim.x + threadIdx.x;
    if (i < NN) {
        int v = g_rowstart[i] + g_boff[i >> 10];
        g_rowstart[i] = v;
        g_fill[i] = v;
    }
}

__global__ void fill_csr_kernel(const int* __restrict__ src,
                                const int* __restrict__ dst) {
    int e = blockIdx.x * blockDim.x + threadIdx.x;
    if (e < NE) {
        int pos = atomicAdd(&g_fill[dst[e]], 1);
        g_csr_src[pos] = src[e];
    }
}

// ---------------- tf32 helpers ----------------
__device__ __forceinline__ void f2tf32_split(float a, uint32_t& hi, uint32_t& lo) {
    asm("cvt.rna.tf32.f32 %0, %1;" : "=r"(hi) : "f"(a));
    float r = a - __uint_as_float(hi);
    asm("cvt.rna.tf32.f32 %0, %1;" : "=r"(lo) : "f"(r));
}

__device__ __forceinline__ void mma_tf32(float* c,
    uint32_t a0, uint32_t a1, uint32_t a2, uint32_t a3,
    uint32_t b0, uint32_t b1)
{
    asm volatile(
        "mma.sync.aligned.m16n8k8.row.col.f32.tf32.tf32.f32 "
        "{%0,%1,%2,%3}, {%4,%5,%6,%7}, {%8,%9}, {%0,%1,%2,%3};"
        : "+f"(c[0]), "+f"(c[1]), "+f"(c[2]), "+f"(c[3])
        : "r"(a0), "r"(a1), "r"(a2), "r"(a3), "r"(b0), "r"(b1));
}

__device__ __forceinline__ float gelu_exact(float x) {
    return 0.5f * x * (1.0f + erff(x * 0.7071067811865476f));
}

// ---------------- pipelined gather of one row's in-neighborhood ----------------
template <bool SRCNORM>
__device__ __forceinline__ float4 gather_row(const float4* __restrict__ hp,
                                             int beg, int end, int lane)
{
    float4 acc = make_float4(0.f, 0.f, 0.f, 0.f);
    int e = beg;
    float4 v[8]; float ns[8];
    bool pro = (e + 8 <= end);
    if (pro) {
        #pragma unroll
        for (int j = 0; j < 8; ++j) {
            int s = __ldg(&g_csr_src[e + j]);
            if (SRCNORM) ns[j] = __ldg(&g_norm_src[s]);
            v[j] = __ldg(&hp[s * 32 + lane]);
        }
    }
    // pipeline: issue next batch's loads before consuming current batch
    for (; e + 16 <= end; e += 8) {
        float4 w[8]; float ws[8];
        #pragma unroll
        for (int j = 0; j < 8; ++j) {
            int s = __ldg(&g_csr_src[e + 8 + j]);
            if (SRCNORM) ws[j] = __ldg(&g_norm_src[s]);
            w[j] = __ldg(&hp[s * 32 + lane]);
        }
        float4 r = make_float4(0.f, 0.f, 0.f, 0.f);
        #pragma unroll
        for (int j = 0; j < 8; ++j) {
            if (SRCNORM) {
                r.x += v[j].x * ns[j]; r.y += v[j].y * ns[j];
                r.z += v[j].z * ns[j]; r.w += v[j].w * ns[j];
            } else {
                r.x += v[j].x; r.y += v[j].y; r.z += v[j].z; r.w += v[j].w;
            }
        }
        acc.x += r.x; acc.y += r.y; acc.z += r.z; acc.w += r.w;
        #pragma unroll
        for (int j = 0; j < 8; ++j) { v[j] = w[j]; if (SRCNORM) ns[j] = ws[j]; }
    }
    if (pro) {
        float4 r = make_float4(0.f, 0.f, 0.f, 0.f);
        #pragma unroll
        for (int j = 0; j < 8; ++j) {
            if (SRCNORM) {
                r.x += v[j].x * ns[j]; r.y += v[j].y * ns[j];
                r.z += v[j].z * ns[j]; r.w += v[j].w * ns[j];
            } else {
                r.x += v[j].x; r.y += v[j].y; r.z += v[j].z; r.w += v[j].w;
            }
        }
        acc.x += r.x; acc.y += r.y; acc.z += r.z; acc.w += r.w;
        e += 8;
    }
    // predicated remainder (< 8 edges) — loads issue in parallel
    #pragma unroll
    for (int j = 0; j < 8; ++j) {
        int ee = e + j;
        if (ee < end) {
            int s = __ldg(&g_csr_src[ee]);
            float4 t = __ldg(&hp[s * 32 + lane]);
            float m = SRCNORM ? __ldg(&g_norm_src[s]) : 1.f;
            acc.x += t.x * m; acc.y += t.y * m;
            acc.z += t.z * m; acc.w += t.w * m;
        }
    }
    return acc;
}

// ---------------- fused gather + tensor-core GEMM + epilogue ----------------
// Block: 256 threads (8 warps), 64 output rows x 128 cols.
// GEMM: 3xTF32 mma.sync (fp32-equivalent). Optional fused LayerNorm (layer 4).
template <bool GELU, bool PRESCALE, bool SRCNORM, bool LNORM>
__global__ void __launch_bounds__(256, 2) gcn_fused_kernel(
    const float* __restrict__ hin,
    const float* __restrict__ W,      // [FD, FD] row-major (k, n)
    const float* __restrict__ bias,   // [FD]
    float* __restrict__ out,          // [NN, FD]
    const float* __restrict__ gamma,
    const float* __restrict__ beta)
{
    extern __shared__ float sm[];
    float* sW = sm;                       // 128 x SW_STR
    float* sA = sm + 128 * SW_STR;        // 64  x SA_STR
    int tid  = threadIdx.x;
    int warp = tid >> 5;
    int lane = tid & 31;
    int rowbase = blockIdx.x * 64;

    // stage W (padded rows)
    {
        float4* sW4 = (float4*)sW;        // row stride SW_STR/4 = 34
        const float4* W4 = (const float4*)W;
        #pragma unroll
        for (int i = 0; i < 16; ++i) {
            int idx = tid + i * 256;
            int k  = idx >> 5;
            int n4 = idx & 31;
            sW4[k * 34 + n4] = __ldg(&W4[idx]);
        }
    }

    // gather phase: warp w handles rows [w*8, w*8+8)
    const float4* hp = (const float4*)hin;
    #pragma unroll 1
    for (int r = 0; r < 8; ++r) {
        int lrow = warp * 8 + r;
        int grow = rowbase + lrow;
        float4 acc = make_float4(0.f, 0.f, 0.f, 0.f);
        if (grow < NN) {
            int beg = __ldg(&g_rowstart[grow]);
            int end = beg + __ldg(&g_cnt_dst[grow]);
            acc = gather_row<SRCNORM>(hp, beg, end, lane);
        }
        ((float4*)sA)[lrow * (SA_STR / 4) + lane] = acc;   // SA_STR/4 = 33
    }
    __syncthreads();

    // ---- tensor-core GEMM: D[64x128] = sA[64x128] @ sW[128x128] (3xTF32) ----
    int g = lane >> 2;        // 0..7
    int t = lane & 3;         // 0..3
    int rtbase = (warp & 3) * 16;
    int chbase = (warp >> 2) * 64;

    float c[8][4];
    #pragma unroll
    for (int n = 0; n < 8; ++n)
        #pragma unroll
        for (int j = 0; j < 4; ++j) c[n][j] = 0.f;

    #pragma unroll 4
    for (int k = 0; k < 16; ++k) {
        int k0 = k * 8;
        float a0f = sA[(rtbase + g)     * SA_STR + k0 + t];
        float a1f = sA[(rtbase + g + 8) * SA_STR + k0 + t];
        float a2f = sA[(rtbase + g)     * SA_STR + k0 + t + 4];
        float a3f = sA[(rtbase + g + 8) * SA_STR + k0 + t + 4];
        uint32_t ah0, al0, ah1, al1, ah2, al2, ah3, al3;
        f2tf32_split(a0f, ah0, al0);
        f2tf32_split(a1f, ah1, al1);
        f2tf32_split(a2f, ah2, al2);
        f2tf32_split(a3f, ah3, al3);

        #pragma unroll
        for (int n = 0; n < 8; ++n) {
            int ncol = chbase + n * 8 + g;
            float b0f = sW[(k0 + t)     * SW_STR + ncol];
            float b1f = sW[(k0 + t + 4) * SW_STR + ncol];
            uint32_t bh0, bl0, bh1, bl1;
            f2tf32_split(b0f, bh0, bl0);
            f2tf32_split(b1f, bh1, bl1);

            mma_tf32(c[n], ah0, ah1, ah2, ah3, bh0, bh1);
            mma_tf32(c[n], ah0, ah1, ah2, ah3, bl0, bl1);
            mma_tf32(c[n], al0, al1, al2, al3, bh0, bh1);
        }
    }

    // ---- epilogue ----
    int row0 = rowbase + rtbase + g;
    int row1 = row0 + 8;
    float nd0 = 0.f, nd1 = 0.f, ns0 = 1.f, ns1 = 1.f;
    if (row0 < NN) { nd0 = __ldg(&g_norm_dst[row0]); if (PRESCALE) ns0 = __ldg(&g_norm_src[row0]); }
    if (row1 < NN) { nd1 = __ldg(&g_norm_dst[row1]); if (PRESCALE) ns1 = __ldg(&g_norm_src[row1]); }

    if (!LNORM) {
        #pragma unroll
        for (int n = 0; n < 8; ++n) {
            int col = chbase + n * 8 + t * 2;
            float2 bv = *(const float2*)(bias + col);
            if (row0 < NN) {
                float ox = c[n][0] * nd0 + bv.x;
                float oy = c[n][1] * nd0 + bv.y;
                if (GELU) { ox = gelu_exact(ox); oy = gelu_exact(oy); }
                if (PRESCALE) { ox *= ns0; oy *= ns0; }
                *(float2*)(out + (size_t)row0 * FD + col) = make_float2(ox, oy);
            }
            if (row1 < NN) {
                float ox = c[n][2] * nd1 + bv.x;
                float oy = c[n][3] * nd1 + bv.y;
                if (GELU) { ox = gelu_exact(ox); oy = gelu_exact(oy); }
                if (PRESCALE) { ox *= ns1; oy *= ns1; }
                *(float2*)(out + (size_t)row1 * FD + col) = make_float2(ox, oy);
            }
        }
    } else {
        // fused LayerNorm: h = c*nd + b, then (h-mu)*rsqrt(var+eps)*gamma + beta
        float s0 = 0.f, q0 = 0.f, s1 = 0.f, q1 = 0.f;
        #pragma unroll
        for (int n = 0; n < 8; ++n) {
            int col = chbase + n * 8 + t * 2;
            float2 bv = *(const float2*)(bias + col);
            float h00 = c[n][0] * nd0 + bv.x;
            float h01 = c[n][1] * nd0 + bv.y;
            float h10 = c[n][2] * nd1 + bv.x;
            float h11 = c[n][3] * nd1 + bv.y;
            c[n][0] = h00; c[n][1] = h01; c[n][2] = h10; c[n][3] = h11;
            s0 += h00 + h01; q0 += h00 * h00 + h01 * h01;
            s1 += h10 + h11; q1 += h10 * h10 + h11 * h11;
        }
        __syncthreads();                    // sA reads done everywhere; reuse as LN scratch
        float2* sLN = (float2*)sA;          // [64][8]
        int slot = (warp >> 2) * 4 + t;
        sLN[(rtbase + g) * 8 + slot]     = make_float2(s0, q0);
        sLN[(rtbase + g + 8) * 8 + slot] = make_float2(s1, q1);
        __syncthreads();
        float ts0 = 0.f, tq0 = 0.f, ts1 = 0.f, tq1 = 0.f;
        #pragma unroll
        for (int k = 0; k < 8; ++k) {
            float2 p0 = sLN[(rtbase + g) * 8 + k];
            float2 p1 = sLN[(rtbase + g + 8) * 8 + k];
            ts0 += p0.x; tq0 += p0.y;
            ts1 += p1.x; tq1 += p1.y;
        }
        float mu0 = ts0 * (1.0f / FD);
        float mu1 = ts1 * (1.0f / FD);
        float inv0 = rsqrtf(fmaxf(tq0 * (1.0f / FD) - mu0 * mu0, 0.f) + 1e-5f);
        float inv1 = rsqrtf(fmaxf(tq1 * (1.0f / FD) - mu1 * mu1, 0.f) + 1e-5f);
        #pragma unroll
        for (int n = 0; n < 8; ++n) {
            int col = chbase + n * 8 + t * 2;
            float2 gv = *(const float2*)(gamma + col);
            float2 bt = *(const float2*)(beta + col);
            if (row0 < NN) {
                float ox = (c[n][0] - mu0) * inv0 * gv.x + bt.x;
                float oy = (c[n][1] - mu0) * inv0 * gv.y + bt.y;
                *(float2*)(out + (size_t)row0 * FD + col) = make_float2(ox, oy);
            }
            if (row1 < NN) {
                float ox = (c[n][2] - mu1) * inv1 * gv.x + bt.x;
                float oy = (c[n][3] - mu1) * inv1 * gv.y + bt.y;
                *(float2*)(out + (size_t)row1 * FD + col) = make_float2(ox, oy);
            }
        }
    }
}

// ---------------- launch ----------------
extern "C" void kernel_launch(void* const* d_in, const int* in_sizes, int n_in,
                              void* d_out, int out_size)
{
    const float* x     = (const float*)d_in[0];
    const int*   src   = (const int*)  d_in[1];
    const int*   dst   = (const int*)  d_in[2];
    const float* Ws[4] = { (const float*)d_in[3], (const float*)d_in[5],
                           (const float*)d_in[7], (const float*)d_in[9] };
    const float* bs[4] = { (const float*)d_in[4], (const float*)d_in[6],
                           (const float*)d_in[8], (const float*)d_in[10] };
    const float* gamma = (const float*)d_in[11];
    const float* beta  = (const float*)d_in[12];
    float* out = (float*)d_out;

    float *h0, *h1;
    cudaGetSymbolAddress((void**)&h0, g_h0);
    cudaGetSymbolAddress((void**)&h1, g_h1);

    cudaFuncSetAttribute(gcn_fused_kernel<true, true, true, false>,
                         cudaFuncAttributeMaxDynamicSharedMemorySize, SMEM_BYTES);
    cudaFuncSetAttribute(gcn_fused_kernel<true, true, false, false>,
                         cudaFuncAttributeMaxDynamicSharedMemorySize, SMEM_BYTES);
    cudaFuncSetAttribute(gcn_fused_kernel<false, false, false, true>,
                         cudaFuncAttributeMaxDynamicSharedMemorySize, SMEM_BYTES);

    const int T = 256;
    zero_counts_kernel<<<(NN + T - 1) / T, T>>>();
    count_deg_kernel<<<(NE + T - 1) / T, T>>>(src, dst);
    make_norm_kernel<<<(NN + T - 1) / T, T>>>();
    scan_block_kernel<<<SCAN_B, SCAN_T>>>();
    scan_bsums_kernel<<<1, 128>>>();
    add_offsets_kernel<<<(NN + T - 1) / T, T>>>();
    fill_csr_kernel<<<(NE + T - 1) / T, T>>>(src, dst);

    const int gemm_blocks = (NN + 63) / 64;
    // L1: fold norm_src into gather (x is raw); L2,L3: prescaled inputs;
    // L4: fused LayerNorm, writes directly to out.
    gcn_fused_kernel<true, true, true, false><<<gemm_blocks, T, SMEM_BYTES>>>(
        x, Ws[0], bs[0], h1, nullptr, nullptr);
    gcn_fused_kernel<true, true, false, false><<<gemm_blocks, T, SMEM_BYTES>>>(
        h1, Ws[1], bs[1], h0, nullptr, nullptr);
    gcn_fused_kernel<true, true, false, false><<<gemm_blocks, T, SMEM_BYTES>>>(
        h0, Ws[2], bs[2], h1, nullptr, nullptr);
    gcn_fused_kernel<false, false, false, true><<<gemm_blocks, T, SMEM_BYTES>>>(
        h1, Ws[3], bs[3], out, gamma, beta);
}

// round 7
// speedup vs baseline: 1.7703x; 1.0748x over previous
#include <cuda_runtime.h>
#include <math.h>
#include <stdint.h>

#define NN 100000
#define NE 1600000
#define FD 128
#define FD4 (FD/4)
#define SCAN_T 1024
#define SCAN_B ((NN + SCAN_T - 1) / SCAN_T)   // 98

// padded smem strides (floats) for bank-conflict-free MMA fragment loads
#define SA_STR 132   // 64 rows
#define SW_STR 136   // 128 rows
#define SMEM_BYTES ((128*SW_STR + 64*SA_STR) * 4)   // 103,424 B

// ---------------- static device scratch ----------------
__device__ float g_h0[(size_t)NN * FD];
__device__ float g_h1[(size_t)NN * FD];
__device__ int   g_cnt_src[NN];
__device__ int   g_cnt_dst[NN];
__device__ float g_norm_src[NN];
__device__ float g_norm_dst[NN];
__device__ int   g_rowstart[NN];
__device__ int   g_fill[NN];
__device__ int   g_bsum[SCAN_B];
__device__ int   g_boff[SCAN_B];
__device__ int   g_csr_src[NE];

// ---------------- setup kernels ----------------
__global__ void zero_counts_kernel() {
    int i = blockIdx.x * blockDim.x + threadIdx.x;
    if (i < NN) { g_cnt_src[i] = 0; g_cnt_dst[i] = 0; }
}

__global__ void count_deg_kernel(const int* __restrict__ src,
                                 const int* __restrict__ dst) {
    int i = blockIdx.x * blockDim.x + threadIdx.x;
    if (i < NE) {
        atomicAdd(&g_cnt_src[src[i]], 1);
        atomicAdd(&g_cnt_dst[dst[i]], 1);
    }
}

__global__ void make_norm_kernel() {
    int i = blockIdx.x * blockDim.x + threadIdx.x;
    if (i < NN) {
        g_norm_src[i] = rsqrtf(fmaxf((float)g_cnt_src[i], 1.0f));
        g_norm_dst[i] = rsqrtf(fmaxf((float)g_cnt_dst[i], 1.0f));
    }
}

__global__ void __launch_bounds__(SCAN_T) scan_block_kernel() {
    __shared__ int s[SCAN_T];
    int t = threadIdx.x;
    int i = blockIdx.x * SCAN_T + t;
    int v = (i < NN) ? g_cnt_dst[i] : 0;
    s[t] = v;
    __syncthreads();
    #pragma unroll
    for (int off = 1; off < SCAN_T; off <<= 1) {
        int x = (t >= off) ? s[t - off] : 0;
        __syncthreads();
        s[t] += x;
        __syncthreads();
    }
    if (i < NN) g_rowstart[i] = s[t] - v;
    if (t == SCAN_T - 1) g_bsum[blockIdx.x] = s[t];
}

__global__ void scan_bsums_kernel() {
    __shared__ int s[128];
    int t = threadIdx.x;
    int v = (t < SCAN_B) ? g_bsum[t] : 0;
    s[t] = v;
    __syncthreads();
    #pragma unroll
    for (int off = 1; off < 128; off <<= 1) {
        int x = (t >= off) ? s[t - off] : 0;
        __syncthreads();
        s[t] += x;
        __syncthreads();
    }
    if (t < SCAN_B) g_boff[t] = s[t] - v;
}

__global__ void add_offsets_kernel() {
    int i = blockIdx.x * blockDim.x + threadIdx.x;
    if (i < NN) {
        int v = g_rowstart[i] + g_boff[i >> 10];
        g_rowstart[i] = v;
        g_fill[i] = v;
    }
}

__global__ void fill_csr_kernel(const int* __restrict__ src,
                                const int* __restrict__ dst) {
    int e = blockIdx.x * blockDim.x + threadIdx.x;
    if (e < NE) {
        int pos = atomicAdd(&g_fill[dst[e]], 1);
        g_csr_src[pos] = src[e];
    }
}

// ---------------- tf32 helpers ----------------
__device__ __forceinline__ void f2tf32_split(float a, uint32_t& hi, uint32_t& lo) {
    asm("cvt.rna.tf32.f32 %0, %1;" : "=r"(hi) : "f"(a));
    float r = a - __uint_as_float(hi);
    asm("cvt.rna.tf32.f32 %0, %1;" : "=r"(lo) : "f"(r));
}

__device__ __forceinline__ void mma_tf32(float* c,
    uint32_t a0, uint32_t a1, uint32_t a2, uint32_t a3,
    uint32_t b0, uint32_t b1)
{
    asm volatile(
        "mma.sync.aligned.m16n8k8.row.col.f32.tf32.tf32.f32 "
        "{%0,%1,%2,%3}, {%4,%5,%6,%7}, {%8,%9}, {%0,%1,%2,%3};"
        : "+f"(c[0]), "+f"(c[1]), "+f"(c[2]), "+f"(c[3])
        : "r"(a0), "r"(a1), "r"(a2), "r"(a3), "r"(b0), "r"(b1));
}

__device__ __forceinline__ float gelu_exact(float x) {
    return 0.5f * x * (1.0f + erff(x * 0.7071067811865476f));
}

// ---------------- fused gather + tensor-core GEMM + epilogue ----------------
// Block: 256 threads (8 warps), 64 output rows x 128 cols.
// Gather: linear-stream over the warp's contiguous CSR edge range with
//         boundary flushing (one pipeline prologue per WARP, not per row).
// GEMM: 3xTF32 mma.sync (fp32-equivalent). Optional fused LayerNorm (layer 4).
template <bool GELU, bool PRESCALE, bool SRCNORM, bool LNORM>
__global__ void __launch_bounds__(256, 2) gcn_fused_kernel(
    const float* __restrict__ hin,
    const float* __restrict__ W,      // [FD, FD] row-major (k, n)
    const float* __restrict__ bias,   // [FD]
    float* __restrict__ out,          // [NN, FD]
    const float* __restrict__ gamma,
    const float* __restrict__ beta)
{
    extern __shared__ float sm[];
    float* sW = sm;                       // 128 x SW_STR
    float* sA = sm + 128 * SW_STR;        // 64  x SA_STR
    __shared__ int sBnd[8][9];            // per-warp row boundaries
    int tid  = threadIdx.x;
    int warp = tid >> 5;
    int lane = tid & 31;
    int rowbase = blockIdx.x * 64;

    // stage W (padded rows)
    {
        float4* sW4 = (float4*)sW;        // row stride SW_STR/4 = 34
        const float4* W4 = (const float4*)W;
        #pragma unroll
        for (int i = 0; i < 16; ++i) {
            int idx = tid + i * 256;
            int k  = idx >> 5;
            int n4 = idx & 31;
            sW4[k * 34 + n4] = __ldg(&W4[idx]);
        }
    }

    // ---- boundary setup: warp w owns rows [r0, r0+8) ----
    int r0 = rowbase + warp * 8;
    {
        int myc = 0;
        int rr = r0 + lane;
        if (lane < 8 && rr < NN) myc = __ldg(&g_cnt_dst[rr]);
        int sum = myc;
        #pragma unroll
        for (int off = 1; off < 8; off <<= 1) {
            int t = __shfl_up_sync(0xFFFFFFFFu, sum, off);
            if ((lane & 7) >= off) sum += t;
        }
        int beg = (r0 < NN) ? __ldg(&g_rowstart[r0]) : 0;
        if (lane == 0) sBnd[warp][0] = beg;
        if (lane < 8)  sBnd[warp][lane + 1] = beg + sum;
    }
    __syncwarp();

    // ---- linear-stream gather ----
    {
        const float4* hp = (const float4*)hin;
        int e   = sBnd[warp][0];
        int end = sBnd[warp][8];
        int cur = 0;
        int next = sBnd[warp][1];
        float4 acc = make_float4(0.f, 0.f, 0.f, 0.f);
        float4* sArow = (float4*)sA;      // stride 33 float4

        float4 v[8]; float ns[8];
        bool pro = (e + 8 <= end);
        if (pro) {
            #pragma unroll
            for (int j = 0; j < 8; ++j) {
                int s = __ldg(&g_csr_src[e + j]);
                if (SRCNORM) ns[j] = __ldg(&g_norm_src[s]);
                v[j] = __ldg(&hp[s * 32 + lane]);
            }
        }
        int ecur = e;
        #pragma unroll 1
        for (; ecur + 16 <= end; ecur += 8) {
            float4 w[8]; float ws[8];
            #pragma unroll
            for (int j = 0; j < 8; ++j) {
                int s = __ldg(&g_csr_src[ecur + 8 + j]);
                if (SRCNORM) ws[j] = __ldg(&g_norm_src[s]);
                w[j] = __ldg(&hp[s * 32 + lane]);
            }
            #pragma unroll
            for (int j = 0; j < 8; ++j) {
                int ee = ecur + j;
                while (ee >= next) {                 // warp-uniform
                    sArow[(warp * 8 + cur) * 33 + lane] = acc;
                    acc = make_float4(0.f, 0.f, 0.f, 0.f);
                    ++cur;
                    next = sBnd[warp][cur + 1];
                }
                if (SRCNORM) {
                    acc.x += v[j].x * ns[j]; acc.y += v[j].y * ns[j];
                    acc.z += v[j].z * ns[j]; acc.w += v[j].w * ns[j];
                } else {
                    acc.x += v[j].x; acc.y += v[j].y;
                    acc.z += v[j].z; acc.w += v[j].w;
                }
            }
            #pragma unroll
            for (int j = 0; j < 8; ++j) { v[j] = w[j]; if (SRCNORM) ns[j] = ws[j]; }
        }
        if (pro) {
            #pragma unroll
            for (int j = 0; j < 8; ++j) {
                int ee = ecur + j;
                while (ee >= next) {
                    sArow[(warp * 8 + cur) * 33 + lane] = acc;
                    acc = make_float4(0.f, 0.f, 0.f, 0.f);
                    ++cur;
                    next = sBnd[warp][cur + 1];
                }
                if (SRCNORM) {
                    acc.x += v[j].x * ns[j]; acc.y += v[j].y * ns[j];
                    acc.z += v[j].z * ns[j]; acc.w += v[j].w * ns[j];
                } else {
                    acc.x += v[j].x; acc.y += v[j].y;
                    acc.z += v[j].z; acc.w += v[j].w;
                }
            }
            ecur += 8;
        }
        // remainder (< 8 edges): parallel predicated loads, then consume
        {
            float4 rv[8]; float rns[8]; int have = end - ecur;
            #pragma unroll
            for (int j = 0; j < 8; ++j) {
                if (j < have) {
                    int s = __ldg(&g_csr_src[ecur + j]);
                    if (SRCNORM) rns[j] = __ldg(&g_norm_src[s]);
                    rv[j] = __ldg(&hp[s * 32 + lane]);
                }
            }
            #pragma unroll
            for (int j = 0; j < 8; ++j) {
                if (j < have) {
                    int ee = ecur + j;
                    while (ee >= next) {
                        sArow[(warp * 8 + cur) * 33 + lane] = acc;
                        acc = make_float4(0.f, 0.f, 0.f, 0.f);
                        ++cur;
                        next = sBnd[warp][cur + 1];
                    }
                    if (SRCNORM) {
                        acc.x += rv[j].x * rns[j]; acc.y += rv[j].y * rns[j];
                        acc.z += rv[j].z * rns[j]; acc.w += rv[j].w * rns[j];
                    } else {
                        acc.x += rv[j].x; acc.y += rv[j].y;
                        acc.z += rv[j].z; acc.w += rv[j].w;
                    }
                }
            }
        }
        // flush current row and zero-fill remaining rows
        #pragma unroll
        for (int rr = 0; rr < 8; ++rr) {
            if (rr >= cur) {
                sArow[(warp * 8 + rr) * 33 + lane] = acc;
                acc = make_float4(0.f, 0.f, 0.f, 0.f);
            }
        }
    }
    __syncthreads();

    // ---- tensor-core GEMM: D[64x128] = sA[64x128] @ sW[128x128] (3xTF32) ----
    int g = lane >> 2;        // 0..7
    int t = lane & 3;         // 0..3
    int rtbase = (warp & 3) * 16;
    int chbase = (warp >> 2) * 64;

    float c[8][4];
    #pragma unroll
    for (int n = 0; n < 8; ++n)
        #pragma unroll
        for (int j = 0; j < 4; ++j) c[n][j] = 0.f;

    #pragma unroll 4
    for (int k = 0; k < 16; ++k) {
        int k0 = k * 8;
        float a0f = sA[(rtbase + g)     * SA_STR + k0 + t];
        float a1f = sA[(rtbase + g + 8) * SA_STR + k0 + t];
        float a2f = sA[(rtbase + g)     * SA_STR + k0 + t + 4];
        float a3f = sA[(rtbase + g + 8) * SA_STR + k0 + t + 4];
        uint32_t ah0, al0, ah1, al1, ah2, al2, ah3, al3;
        f2tf32_split(a0f, ah0, al0);
        f2tf32_split(a1f, ah1, al1);
        f2tf32_split(a2f, ah2, al2);
        f2tf32_split(a3f, ah3, al3);

        #pragma unroll
        for (int n = 0; n < 8; ++n) {
            int ncol = chbase + n * 8 + g;
            float b0f = sW[(k0 + t)     * SW_STR + ncol];
            float b1f = sW[(k0 + t + 4) * SW_STR + ncol];
            uint32_t bh0, bl0, bh1, bl1;
            f2tf32_split(b0f, bh0, bl0);
            f2tf32_split(b1f, bh1, bl1);

            mma_tf32(c[n], ah0, ah1, ah2, ah3, bh0, bh1);
            mma_tf32(c[n], ah0, ah1, ah2, ah3, bl0, bl1);
            mma_tf32(c[n], al0, al1, al2, al3, bh0, bh1);
        }
    }

    // ---- epilogue ----
    int row0 = rowbase + rtbase + g;
    int row1 = row0 + 8;
    float nd0 = 0.f, nd1 = 0.f, ns0 = 1.f, ns1 = 1.f;
    if (row0 < NN) { nd0 = __ldg(&g_norm_dst[row0]); if (PRESCALE) ns0 = __ldg(&g_norm_src[row0]); }
    if (row1 < NN) { nd1 = __ldg(&g_norm_dst[row1]); if (PRESCALE) ns1 = __ldg(&g_norm_src[row1]); }

    if (!LNORM) {
        #pragma unroll
        for (int n = 0; n < 8; ++n) {
            int col = chbase + n * 8 + t * 2;
            float2 bv = *(const float2*)(bias + col);
            if (row0 < NN) {
                float ox = c[n][0] * nd0 + bv.x;
                float oy = c[n][1] * nd0 + bv.y;
                if (GELU) { ox = gelu_exact(ox); oy = gelu_exact(oy); }
                if (PRESCALE) { ox *= ns0; oy *= ns0; }
                *(float2*)(out + (size_t)row0 * FD + col) = make_float2(ox, oy);
            }
            if (row1 < NN) {
                float ox = c[n][2] * nd1 + bv.x;
                float oy = c[n][3] * nd1 + bv.y;
                if (GELU) { ox = gelu_exact(ox); oy = gelu_exact(oy); }
                if (PRESCALE) { ox *= ns1; oy *= ns1; }
                *(float2*)(out + (size_t)row1 * FD + col) = make_float2(ox, oy);
            }
        }
    } else {
        float s0 = 0.f, q0 = 0.f, s1 = 0.f, q1 = 0.f;
        #pragma unroll
        for (int n = 0; n < 8; ++n) {
            int col = chbase + n * 8 + t * 2;
            float2 bv = *(const float2*)(bias + col);
            float h00 = c[n][0] * nd0 + bv.x;
            float h01 = c[n][1] * nd0 + bv.y;
            float h10 = c[n][2] * nd1 + bv.x;
            float h11 = c[n][3] * nd1 + bv.y;
            c[n][0] = h00; c[n][1] = h01; c[n][2] = h10; c[n][3] = h11;
            s0 += h00 + h01; q0 += h00 * h00 + h01 * h01;
            s1 += h10 + h11; q1 += h10 * h10 + h11 * h11;
        }
        __syncthreads();
        float2* sLN = (float2*)sA;          // [64][8]
        int slot = (warp >> 2) * 4 + t;
        sLN[(rtbase + g) * 8 + slot]     = make_float2(s0, q0);
        sLN[(rtbase + g + 8) * 8 + slot] = make_float2(s1, q1);
        __syncthreads();
        float ts0 = 0.f, tq0 = 0.f, ts1 = 0.f, tq1 = 0.f;
        #pragma unroll
        for (int k = 0; k < 8; ++k) {
            float2 p0 = sLN[(rtbase + g) * 8 + k];
            float2 p1 = sLN[(rtbase + g + 8) * 8 + k];
            ts0 += p0.x; tq0 += p0.y;
            ts1 += p1.x; tq1 += p1.y;
        }
        float mu0 = ts0 * (1.0f / FD);
        float mu1 = ts1 * (1.0f / FD);
        float inv0 = rsqrtf(fmaxf(tq0 * (1.0f / FD) - mu0 * mu0, 0.f) + 1e-5f);
        float inv1 = rsqrtf(fmaxf(tq1 * (1.0f / FD) - mu1 * mu1, 0.f) + 1e-5f);
        #pragma unroll
        for (int n = 0; n < 8; ++n) {
            int col = chbase + n * 8 + t * 2;
            float2 gv = *(const float2*)(gamma + col);
            float2 bt = *(const float2*)(beta + col);
            if (row0 < NN) {
                float ox = (c[n][0] - mu0) * inv0 * gv.x + bt.x;
                float oy = (c[n][1] - mu0) * inv0 * gv.y + bt.y;
                *(float2*)(out + (size_t)row0 * FD + col) = make_float2(ox, oy);
            }
            if (row1 < NN) {
                float ox = (c[n][2] - mu1) * inv1 * gv.x + bt.x;
                float oy = (c[n][3] - mu1) * inv1 * gv.y + bt.y;
                *(float2*)(out + (size_t)row1 * FD + col) = make_float2(ox, oy);
            }
        }
    }
}

// ---------------- launch ----------------
extern "C" void kernel_launch(void* const* d_in, const int* in_sizes, int n_in,
                              void* d_out, int out_size)
{
    const float* x     = (const float*)d_in[0];
    const int*   src   = (const int*)  d_in[1];
    const int*   dst   = (const int*)  d_in[2];
    const float* Ws[4] = { (const float*)d_in[3], (const float*)d_in[5],
                           (const float*)d_in[7], (const float*)d_in[9] };
    const float* bs[4] = { (const float*)d_in[4], (const float*)d_in[6],
                           (const float*)d_in[8], (const float*)d_in[10] };
    const float* gamma = (const float*)d_in[11];
    const float* beta  = (const float*)d_in[12];
    float* out = (float*)d_out;

    float *h0, *h1;
    cudaGetSymbolAddress((void**)&h0, g_h0);
    cudaGetSymbolAddress((void**)&h1, g_h1);

    cudaFuncSetAttribute(gcn_fused_kernel<true, true, true, false>,
                         cudaFuncAttributeMaxDynamicSharedMemorySize, SMEM_BYTES);
    cudaFuncSetAttribute(gcn_fused_kernel<true, true, false, false>,
                         cudaFuncAttributeMaxDynamicSharedMemorySize, SMEM_BYTES);
    cudaFuncSetAttribute(gcn_fused_kernel<false, false, false, true>,
                         cudaFuncAttributeMaxDynamicSharedMemorySize, SMEM_BYTES);

    const int T = 256;
    zero_counts_kernel<<<(NN + T - 1) / T, T>>>();
    count_deg_kernel<<<(NE + T - 1) / T, T>>>(src, dst);
    make_norm_kernel<<<(NN + T - 1) / T, T>>>();
    scan_block_kernel<<<SCAN_B, SCAN_T>>>();
    scan_bsums_kernel<<<1, 128>>>();
    add_offsets_kernel<<<(NN + T - 1) / T, T>>>();
    fill_csr_kernel<<<(NE + T - 1) / T, T>>>(src, dst);

    const int gemm_blocks = (NN + 63) / 64;
    gcn_fused_kernel<true, true, true, false><<<gemm_blocks, T, SMEM_BYTES>>>(
        x, Ws[0], bs[0], h1, nullptr, nullptr);
    gcn_fused_kernel<true, true, false, false><<<gemm_blocks, T, SMEM_BYTES>>>(
        h1, Ws[1], bs[1], h0, nullptr, nullptr);
    gcn_fused_kernel<true, true, false, false><<<gemm_blocks, T, SMEM_BYTES>>>(
        h0, Ws[2], bs[2], h1, nullptr, nullptr);
    gcn_fused_kernel<false, false, false, true><<<gemm_blocks, T, SMEM_BYTES>>>(
        h1, Ws[3], bs[3], out, gamma, beta);
}